// round 1
// baseline (speedup 1.0000x reference)
#include <cuda_runtime.h>
#include <math.h>

#define NN 50000
#define NE 1600000

// ---------------- scratch (static device arrays; no runtime alloc) ----------
__device__ float  d_Q[NN * 256];       // [n][ch(32)][band(8)]  q pre-scaled
__device__ float  d_K[NN * 256];
__device__ float  d_V[NN * 256];
__device__ float  d_H[NN * 256];       // skip first, then h (ELU output)
__device__ float  d_HW[NN * 32];       // h @ Wg
__device__ int    d_csr_src[NE];
__device__ float2 d_csr_attr[NE];
__device__ float  d_csr_coef[NE];      // dis[src] * w
__device__ int    d_count[NN];
__device__ int    d_cursor[NN];
__device__ int    d_offsets[NN + 1];
__device__ float  d_degw[NN];
__device__ float  d_dis[NN];

// ---------------- CSR build --------------------------------------------------
__global__ void zero_kernel() {
    int i = blockIdx.x * blockDim.x + threadIdx.x;
    if (i < NN) { d_count[i] = 0; d_cursor[i] = 0; d_degw[i] = 0.f; }
}

__global__ void hist_kernel(const int* __restrict__ ei, const float* __restrict__ ea) {
    int e = blockIdx.x * blockDim.x + threadIdx.x;
    if (e < NE) {
        int dst = ei[NE + e];
        atomicAdd(&d_count[dst], 1);
        atomicAdd(&d_degw[dst], ea[2 * e + 1]);
    }
}

// single-block exclusive scan over d_count -> d_offsets
__global__ void scan_kernel() {
    __shared__ int wsum[32];
    __shared__ int carry;
    int tid = threadIdx.x, lane = tid & 31, wid = tid >> 5;
    if (tid == 0) carry = 0;
    __syncthreads();
    for (int base = 0; base < NN; base += 1024) {
        int i = base + tid;
        int v = (i < NN) ? d_count[i] : 0;
        int s = v;
        #pragma unroll
        for (int off = 1; off < 32; off <<= 1) {
            int t = __shfl_up_sync(0xffffffffu, s, off);
            if (lane >= off) s += t;
        }
        if (lane == 31) wsum[wid] = s;
        __syncthreads();
        if (wid == 0) {
            int ws = wsum[lane];
            #pragma unroll
            for (int off = 1; off < 32; off <<= 1) {
                int t = __shfl_up_sync(0xffffffffu, ws, off);
                if (lane >= off) ws += t;
            }
            wsum[lane] = ws;
        }
        __syncthreads();
        int wexcl = wid ? wsum[wid - 1] : 0;
        if (i < NN) d_offsets[i] = carry + wexcl + (s - v);
        int tot = wsum[31];
        __syncthreads();
        if (tid == 0) carry += tot;
        __syncthreads();
    }
    if (threadIdx.x == 0) d_offsets[NN] = carry;
}

__global__ void dis_kernel() {
    int i = blockIdx.x * blockDim.x + threadIdx.x;
    if (i < NN) d_dis[i] = rsqrtf(d_degw[i] + 2.0f);
}

__global__ void scatter_kernel(const int* __restrict__ ei, const float* __restrict__ ea) {
    int e = blockIdx.x * blockDim.x + threadIdx.x;
    if (e < NE) {
        int src = ei[e], dst = ei[NE + e];
        int pos = d_offsets[dst] + atomicAdd(&d_cursor[dst], 1);
        float ax = ea[2 * e], ay = ea[2 * e + 1];
        d_csr_src[pos]  = src;
        d_csr_attr[pos] = make_float2(ax, ay);
        d_csr_coef[pos] = d_dis[src] * ay;
    }
}

// ---------------- QKV + skip precompute -------------------------------------
// layout [n][ch][band]; q pre-scaled by inv_sqrt(C)*log2(e)
__global__ void qkv_kernel(const float* __restrict__ x,
                           const float* __restrict__ Wq, const float* __restrict__ bq,
                           const float* __restrict__ Wk, const float* __restrict__ bk,
                           const float* __restrict__ Wv, const float* __restrict__ bv,
                           const float* __restrict__ Wsk, const float* __restrict__ bsk) {
    int lane = threadIdx.x & 31;
    int warp = (blockIdx.x * blockDim.x + threadIdx.x) >> 5;
    int nwarps = (gridDim.x * blockDim.x) >> 5;
    float wq[8], wk[8], wv[8], ws[8];
    #pragma unroll
    for (int i = 0; i < 8; i++) {
        wq[i] = Wq[i * 32 + lane];
        wk[i] = Wk[i * 32 + lane];
        wv[i] = Wv[i * 32 + lane];
        ws[i] = Wsk[i * 32 + lane];
    }
    float bqv = bq[lane], bkv = bk[lane], bvv = bv[lane], bsv = bsk[lane];
    const float QS = 0.25f * 1.4426950408889634f;  // 1/sqrt(16) * log2(e)

    for (int n = warp; n < NN; n += nwarps) {
        float x0 = x[n * 64 + lane];
        float x1 = x[n * 64 + 32 + lane];
        float q[8], k[8], v[8], s[8];
        #pragma unroll
        for (int b = 0; b < 8; b++) {
            float aq = bqv, ak = bkv, av = bvv, asv = bsv;
            #pragma unroll
            for (int i = 0; i < 8; i++) {
                const int f = b * 8 + i;
                float xv = __shfl_sync(0xffffffffu, (f < 32) ? x0 : x1, f & 31);
                aq += xv * wq[i]; ak += xv * wk[i]; av += xv * wv[i]; asv += xv * ws[i];
            }
            q[b] = aq * QS; k[b] = ak; v[b] = av; s[b] = asv;
        }
        float4* Qp = (float4*)&d_Q[n * 256 + lane * 8];
        Qp[0] = make_float4(q[0], q[1], q[2], q[3]);
        Qp[1] = make_float4(q[4], q[5], q[6], q[7]);
        float4* Kp = (float4*)&d_K[n * 256 + lane * 8];
        Kp[0] = make_float4(k[0], k[1], k[2], k[3]);
        Kp[1] = make_float4(k[4], k[5], k[6], k[7]);
        float4* Vp = (float4*)&d_V[n * 256 + lane * 8];
        Vp[0] = make_float4(v[0], v[1], v[2], v[3]);
        Vp[1] = make_float4(v[4], v[5], v[6], v[7]);
        float4* Hp = (float4*)&d_H[n * 256 + lane * 8];
        Hp[0] = make_float4(s[0], s[1], s[2], s[3]);
        Hp[1] = make_float4(s[4], s[5], s[6], s[7]);
    }
}

// ---------------- attention: one warp per dst, all 8 bands, online softmax ---
__global__ void attn_kernel(const float* __restrict__ We) {
    int lane = threadIdx.x & 31;
    int dst = (blockIdx.x * blockDim.x + threadIdx.x) >> 5;
    if (dst >= NN) return;
    float we0 = We[lane], we1 = We[32 + lane];

    float q[8], m[8], z[8], acc[8];
    {
        const float4* Qp = (const float4*)&d_Q[dst * 256 + lane * 8];
        float4 q0 = Qp[0], q1 = Qp[1];
        q[0] = q0.x; q[1] = q0.y; q[2] = q0.z; q[3] = q0.w;
        q[4] = q1.x; q[5] = q1.y; q[6] = q1.z; q[7] = q1.w;
    }
    #pragma unroll
    for (int b = 0; b < 8; b++) { m[b] = -INFINITY; z[b] = 0.f; acc[b] = 0.f; }

    int start = d_offsets[dst], end = d_offsets[dst + 1];
    for (int base = start; base < end; base += 32) {
        int eidx = base + lane;
        int sreg = 0; float ax = 0.f, ay = 0.f;
        if (eidx < end) {
            sreg = d_csr_src[eidx];
            float2 a = d_csr_attr[eidx];
            ax = a.x; ay = a.y;
        }
        int cnt = min(32, end - base);
        for (int t = 0; t < cnt; t++) {
            int src   = __shfl_sync(0xffffffffu, sreg, t);
            float eax = __shfl_sync(0xffffffffu, ax, t);
            float eay = __shfl_sync(0xffffffffu, ay, t);
            float ev = eax * we0 + eay * we1;
            const float4* Kp = (const float4*)&d_K[src * 256 + lane * 8];
            float4 k0 = Kp[0], k1 = Kp[1];
            const float4* Vp = (const float4*)&d_V[src * 256 + lane * 8];
            float4 v0 = Vp[0], v1 = Vp[1];
            float kk[8] = {k0.x, k0.y, k0.z, k0.w, k1.x, k1.y, k1.z, k1.w};
            float vv[8] = {v0.x, v0.y, v0.z, v0.w, v1.x, v1.y, v1.z, v1.w};
            #pragma unroll
            for (int b = 0; b < 8; b++) {
                float p = q[b] * (kk[b] + ev);
                p += __shfl_xor_sync(0xffffffffu, p, 1);
                p += __shfl_xor_sync(0xffffffffu, p, 2);
                p += __shfl_xor_sync(0xffffffffu, p, 4);
                p += __shfl_xor_sync(0xffffffffu, p, 8);
                // p = base-2 logit, identical across each 16-lane head group
                float vb = vv[b] + ev;
                if (p > m[b]) {
                    float sc = exp2f(m[b] - p);
                    z[b]   = z[b] * sc + 1.0f;
                    acc[b] = acc[b] * sc + vb;
                    m[b] = p;
                } else {
                    float pe = exp2f(p - m[b]);
                    z[b]   += pe;
                    acc[b] += pe * vb;
                }
            }
        }
    }

    float4* Hp = (float4*)&d_H[dst * 256 + lane * 8];
    float4 h0 = Hp[0], h1 = Hp[1];
    float hs[8] = {h0.x, h0.y, h0.z, h0.w, h1.x, h1.y, h1.z, h1.w};
    float o[8];
    #pragma unroll
    for (int b = 0; b < 8; b++) {
        float agg = (z[b] > 0.f) ? acc[b] / z[b] : 0.f;
        float t = agg + hs[b];
        o[b] = (t > 0.f) ? t : 0.1f * (__expf(t) - 1.0f);
    }
    Hp[0] = make_float4(o[0], o[1], o[2], o[3]);
    Hp[1] = make_float4(o[4], o[5], o[6], o[7]);
}

// ---------------- hw = h @ Wg ------------------------------------------------
__global__ void hw_kernel(const float* __restrict__ Wg) {
    __shared__ float wgs[256 * 32];
    // reorder rows: memory flat index t = ch*8+band -> Wg row r = band*32+ch
    for (int idx = threadIdx.x; idx < 8192; idx += blockDim.x) {
        int t = idx >> 5, j = idx & 31;
        wgs[idx] = Wg[(((t & 7) << 5) + (t >> 3)) * 32 + j];
    }
    __syncthreads();
    int lane = threadIdx.x & 31;
    int warp = (blockIdx.x * blockDim.x + threadIdx.x) >> 5;
    int nwarps = (gridDim.x * blockDim.x) >> 5;
    for (int n = warp; n < NN; n += nwarps) {
        const float4* Hp = (const float4*)&d_H[n * 256];
        float a = 0.f;
        #pragma unroll
        for (int c = 0; c < 64; c++) {
            float4 hv = Hp[c];  // uniform per warp -> broadcast
            a += hv.x * wgs[(4 * c + 0) * 32 + lane];
            a += hv.y * wgs[(4 * c + 1) * 32 + lane];
            a += hv.z * wgs[(4 * c + 2) * 32 + lane];
            a += hv.w * wgs[(4 * c + 3) * 32 + lane];
        }
        d_HW[n * 32 + lane] = a;
    }
}

// ---------------- final normalized propagation -------------------------------
__global__ void final_kernel(const float* __restrict__ bg, float* __restrict__ out) {
    int lane = threadIdx.x & 31;
    int dst = (blockIdx.x * blockDim.x + threadIdx.x) >> 5;
    if (dst >= NN) return;
    float dd = d_dis[dst];
    float acc = 2.0f * dd * d_HW[dst * 32 + lane];  // self loop: dis*2*dis*hw (one dd factored)
    int start = d_offsets[dst], end = d_offsets[dst + 1];
    for (int base = start; base < end; base += 32) {
        int eidx = base + lane;
        int sreg = 0; float creg = 0.f;
        if (eidx < end) { sreg = d_csr_src[eidx]; creg = d_csr_coef[eidx]; }
        int cnt = min(32, end - base);
        for (int t = 0; t < cnt; t++) {
            int src = __shfl_sync(0xffffffffu, sreg, t);
            float c = __shfl_sync(0xffffffffu, creg, t);
            acc += c * d_HW[src * 32 + lane];
        }
    }
    out[dst * 32 + lane] = bg[lane] + dd * acc;
}

// ---------------- launch -----------------------------------------------------
extern "C" void kernel_launch(void* const* d_in, const int* in_sizes, int n_in,
                              void* d_out, int out_size) {
    const float* x   = (const float*)d_in[0];
    const float* ea  = (const float*)d_in[1];
    const float* Wq  = (const float*)d_in[2];
    const float* bq  = (const float*)d_in[3];
    const float* Wk  = (const float*)d_in[4];
    const float* bk  = (const float*)d_in[5];
    const float* Wv  = (const float*)d_in[6];
    const float* bv  = (const float*)d_in[7];
    const float* We  = (const float*)d_in[8];
    const float* Wsk = (const float*)d_in[9];
    const float* bsk = (const float*)d_in[10];
    const float* Wg  = (const float*)d_in[11];
    const float* bg  = (const float*)d_in[12];
    const int*   ei  = (const int*)d_in[13];
    float* out = (float*)d_out;

    zero_kernel<<<(NN + 255) / 256, 256>>>();
    hist_kernel<<<(NE + 255) / 256, 256>>>(ei, ea);
    scan_kernel<<<1, 1024>>>();
    dis_kernel<<<(NN + 255) / 256, 256>>>();
    scatter_kernel<<<(NE + 255) / 256, 256>>>(ei, ea);
    qkv_kernel<<<400, 256>>>(x, Wq, bq, Wk, bk, Wv, bv, Wsk, bsk);
    attn_kernel<<<(NN * 32 + 255) / 256, 256>>>(We);
    hw_kernel<<<296, 256>>>(Wg);
    final_kernel<<<(NN * 32 + 255) / 256, 256>>>(bg, out);
}

// round 2
// speedup vs baseline: 1.5958x; 1.5958x over previous
#include <cuda_runtime.h>
#include <cuda_fp16.h>
#include <math.h>

#define NN 50000
#define NE 1600000

// ---------------- scratch (static device arrays) -----------------------------
__device__ float  d_Q[NN * 256];        // [n][band(8)][hc(32)]  q pre-scaled by 0.25*log2e
__device__ __half d_Kh[NN * 256];       // [n][band][hc] fp16
__device__ __half d_Vh[NN * 256];
__device__ float  d_H[NN * 256];        // skip first, then h (post-ELU)
__device__ float  d_HW[NN * 32];
__device__ int    d_csr_src[NE];
__device__ __half d_csr_eh[NE * 32];    // per-edge e = edge_attrs @ We, [hc] fp16
__device__ float  d_csr_coef[NE];       // dis[src] * w
__device__ int    d_count[NN];
__device__ int    d_cursor[NN];
__device__ int    d_offsets[NN + 1];
__device__ float  d_degw[NN];
__device__ float  d_dis[NN];

__device__ __forceinline__ float ex2f(float x) {
    float y; asm("ex2.approx.f32 %0, %1;" : "=f"(y) : "f"(x)); return y;
}
__device__ __forceinline__ void cvt8(const uint4 u, float* f) {
    float2 a;
    a = __half22float2(*(const __half2*)&u.x); f[0] = a.x; f[1] = a.y;
    a = __half22float2(*(const __half2*)&u.y); f[2] = a.x; f[3] = a.y;
    a = __half22float2(*(const __half2*)&u.z); f[4] = a.x; f[5] = a.y;
    a = __half22float2(*(const __half2*)&u.w); f[6] = a.x; f[7] = a.y;
}

// ---------------- CSR build --------------------------------------------------
__global__ void zero_kernel() {
    int i = blockIdx.x * blockDim.x + threadIdx.x;
    if (i < NN) { d_count[i] = 0; d_cursor[i] = 0; d_degw[i] = 0.f; }
}

__global__ void hist_kernel(const int* __restrict__ ei, const float* __restrict__ ea) {
    int e = blockIdx.x * blockDim.x + threadIdx.x;
    if (e < NE) {
        int dst = ei[NE + e];
        atomicAdd(&d_count[dst], 1);
        atomicAdd(&d_degw[dst], ea[2 * e + 1]);
    }
}

__global__ void scan_kernel() {
    __shared__ int wsum[32];
    __shared__ int carry;
    int tid = threadIdx.x, lane = tid & 31, wid = tid >> 5;
    if (tid == 0) carry = 0;
    __syncthreads();
    for (int base = 0; base < NN; base += 1024) {
        int i = base + tid;
        int v = (i < NN) ? d_count[i] : 0;
        int s = v;
        #pragma unroll
        for (int off = 1; off < 32; off <<= 1) {
            int t = __shfl_up_sync(0xffffffffu, s, off);
            if (lane >= off) s += t;
        }
        if (lane == 31) wsum[wid] = s;
        __syncthreads();
        if (wid == 0) {
            int ws = wsum[lane];
            #pragma unroll
            for (int off = 1; off < 32; off <<= 1) {
                int t = __shfl_up_sync(0xffffffffu, ws, off);
                if (lane >= off) ws += t;
            }
            wsum[lane] = ws;
        }
        __syncthreads();
        int wexcl = wid ? wsum[wid - 1] : 0;
        if (i < NN) d_offsets[i] = carry + wexcl + (s - v);
        int tot = wsum[31];
        __syncthreads();
        if (tid == 0) carry += tot;
        __syncthreads();
    }
    if (threadIdx.x == 0) d_offsets[NN] = carry;
}

__global__ void dis_kernel() {
    int i = blockIdx.x * blockDim.x + threadIdx.x;
    if (i < NN) d_dis[i] = rsqrtf(d_degw[i] + 2.0f);
}

__global__ void scatter_kernel(const int* __restrict__ ei, const float* __restrict__ ea,
                               const float* __restrict__ We) {
    int e = blockIdx.x * blockDim.x + threadIdx.x;
    if (e < NE) {
        int src = ei[e], dst = ei[NE + e];
        int pos = d_offsets[dst] + atomicAdd(&d_cursor[dst], 1);
        float ax = ea[2 * e], ay = ea[2 * e + 1];
        d_csr_src[pos]  = src;
        d_csr_coef[pos] = d_dis[src] * ay;
        __half2* ep = (__half2*)&d_csr_eh[pos * 32];
        #pragma unroll
        for (int j = 0; j < 16; j++) {
            float e0 = fmaf(ax, __ldg(&We[2 * j]),     ay * __ldg(&We[32 + 2 * j]));
            float e1 = fmaf(ax, __ldg(&We[2 * j + 1]), ay * __ldg(&We[32 + 2 * j + 1]));
            ep[j] = __floats2half2_rn(e0, e1);
        }
    }
}

// ---------------- QKV + skip precompute, layout [n][band][hc] ----------------
__global__ void qkv_kernel(const float* __restrict__ x,
                           const float* __restrict__ Wq, const float* __restrict__ bq,
                           const float* __restrict__ Wk, const float* __restrict__ bk,
                           const float* __restrict__ Wv, const float* __restrict__ bv,
                           const float* __restrict__ Wsk, const float* __restrict__ bsk) {
    int lane = threadIdx.x & 31;
    int warp = (blockIdx.x * blockDim.x + threadIdx.x) >> 5;
    int nwarps = (gridDim.x * blockDim.x) >> 5;
    float wq[8], wk[8], wv[8], ws[8];
    #pragma unroll
    for (int i = 0; i < 8; i++) {
        wq[i] = Wq[i * 32 + lane];
        wk[i] = Wk[i * 32 + lane];
        wv[i] = Wv[i * 32 + lane];
        ws[i] = Wsk[i * 32 + lane];
    }
    float bqv = bq[lane], bkv = bk[lane], bvv = bv[lane], bsv = bsk[lane];
    const float QS = 0.25f * 1.4426950408889634f;  // 1/sqrt(16) * log2(e)

    for (int n = warp; n < NN; n += nwarps) {
        float x0 = x[n * 64 + lane];
        float x1 = x[n * 64 + 32 + lane];
        #pragma unroll
        for (int b = 0; b < 8; b++) {
            float aq = bqv, ak = bkv, av = bvv, asv = bsv;
            #pragma unroll
            for (int i = 0; i < 8; i++) {
                const int f = b * 8 + i;
                float xv = __shfl_sync(0xffffffffu, (f < 32) ? x0 : x1, f & 31);
                aq += xv * wq[i]; ak += xv * wk[i]; av += xv * wv[i]; asv += xv * ws[i];
            }
            int o = n * 256 + b * 32 + lane;
            d_Q[o]  = aq * QS;
            d_Kh[o] = __float2half(ak);
            d_Vh[o] = __float2half(av);
            d_H[o]  = asv;
        }
    }
}

// ---------------- attention: warp per dst, lane per (band,head), 2 edges/warp
__global__ void __launch_bounds__(256, 2) attn_kernel() {
    int tid = blockIdx.x * blockDim.x + threadIdx.x;
    int dst = tid >> 5;
    if (dst >= NN) return;
    int lane = threadIdx.x & 31;
    int pair = lane & 15;          // (band<<1)|head
    int hf   = lane >> 4;          // which of two edges this lane serves
    int hoff = (pair & 1) << 4;    // head*16 offset into e-row

    float q[16];
    {
        const float4* Qp = (const float4*)&d_Q[dst * 256 + pair * 16];
        float4 t0 = Qp[0], t1 = Qp[1], t2 = Qp[2], t3 = Qp[3];
        q[0]=t0.x; q[1]=t0.y; q[2]=t0.z; q[3]=t0.w;
        q[4]=t1.x; q[5]=t1.y; q[6]=t1.z; q[7]=t1.w;
        q[8]=t2.x; q[9]=t2.y; q[10]=t2.z; q[11]=t2.w;
        q[12]=t3.x; q[13]=t3.y; q[14]=t3.z; q[15]=t3.w;
    }
    float acc[16];
    #pragma unroll
    for (int c = 0; c < 16; c++) acc[c] = 0.f;
    float z = 0.f;

    int start = d_offsets[dst], end = d_offsets[dst + 1];
    for (int e = start + hf; e < end; e += 2) {
        int src = d_csr_src[e];
        const uint4* ep = (const uint4*)&d_csr_eh[e * 32 + hoff];
        uint4 eu0 = ep[0], eu1 = ep[1];
        const uint4* kp = (const uint4*)&d_Kh[src * 256 + pair * 16];
        uint4 ku0 = kp[0], ku1 = kp[1];
        const uint4* vp = (const uint4*)&d_Vh[src * 256 + pair * 16];
        uint4 vu0 = vp[0], vu1 = vp[1];
        float ef[16], kf[16], vf[16];
        cvt8(eu0, ef); cvt8(eu1, ef + 8);
        cvt8(ku0, kf); cvt8(ku1, kf + 8);
        cvt8(vu0, vf); cvt8(vu1, vf + 8);
        float s = 0.f;
        #pragma unroll
        for (int c = 0; c < 16; c++) s = fmaf(q[c], kf[c] + ef[c], s);
        float p = ex2f(s);   // q pre-scaled -> base-2 softmax, no max needed (tiny logits)
        z += p;
        #pragma unroll
        for (int c = 0; c < 16; c++) acc[c] = fmaf(p, vf[c] + ef[c], acc[c]);
    }

    z += __shfl_xor_sync(0xffffffffu, z, 16);
    #pragma unroll
    for (int c = 0; c < 16; c++) acc[c] += __shfl_xor_sync(0xffffffffu, acc[c], 16);

    if (hf == 0) {
        float rz = (z > 0.f) ? 1.0f / z : 0.f;
        const float* Hp = &d_H[dst * 256 + pair * 16];
        float o[16];
        #pragma unroll
        for (int c = 0; c < 16; c++) {
            float t = fmaf(acc[c], rz, Hp[c]);
            o[c] = (t > 0.f) ? t : 0.1f * (__expf(t) - 1.0f);
        }
        float4* Op = (float4*)&d_H[dst * 256 + pair * 16];
        Op[0] = make_float4(o[0], o[1], o[2], o[3]);
        Op[1] = make_float4(o[4], o[5], o[6], o[7]);
        Op[2] = make_float4(o[8], o[9], o[10], o[11]);
        Op[3] = make_float4(o[12], o[13], o[14], o[15]);
    }
}

// ---------------- hw = h @ Wg  (layouts now match Wg row order directly) -----
__global__ void hw_kernel(const float* __restrict__ Wg) {
    __shared__ float wgs[256 * 32];
    for (int idx = threadIdx.x; idx < 8192; idx += blockDim.x)
        wgs[idx] = Wg[idx];
    __syncthreads();
    int lane = threadIdx.x & 31;
    int warp = (blockIdx.x * blockDim.x + threadIdx.x) >> 5;
    int nwarps = (gridDim.x * blockDim.x) >> 5;
    for (int n = warp; n < NN; n += nwarps) {
        const float4* Hp = (const float4*)&d_H[n * 256];
        float a = 0.f;
        #pragma unroll
        for (int c = 0; c < 64; c++) {
            float4 hv = Hp[c];  // uniform per warp -> broadcast
            a += hv.x * wgs[(4 * c + 0) * 32 + lane];
            a += hv.y * wgs[(4 * c + 1) * 32 + lane];
            a += hv.z * wgs[(4 * c + 2) * 32 + lane];
            a += hv.w * wgs[(4 * c + 3) * 32 + lane];
        }
        d_HW[n * 32 + lane] = a;
    }
}

// ---------------- final normalized propagation -------------------------------
__global__ void final_kernel(const float* __restrict__ bg, float* __restrict__ out) {
    int lane = threadIdx.x & 31;
    int dst = (blockIdx.x * blockDim.x + threadIdx.x) >> 5;
    if (dst >= NN) return;
    float dd = d_dis[dst];
    float acc = 2.0f * dd * d_HW[dst * 32 + lane];  // self loop
    int start = d_offsets[dst], end = d_offsets[dst + 1];
    for (int t = start; t < end; t++) {
        int src = d_csr_src[t];        // uniform across warp -> broadcast load
        float c = d_csr_coef[t];
        acc = fmaf(c, d_HW[src * 32 + lane], acc);
    }
    out[dst * 32 + lane] = bg[lane] + dd * acc;
}

// ---------------- launch -----------------------------------------------------
extern "C" void kernel_launch(void* const* d_in, const int* in_sizes, int n_in,
                              void* d_out, int out_size) {
    const float* x   = (const float*)d_in[0];
    const float* ea  = (const float*)d_in[1];
    const float* Wq  = (const float*)d_in[2];
    const float* bq  = (const float*)d_in[3];
    const float* Wk  = (const float*)d_in[4];
    const float* bk  = (const float*)d_in[5];
    const float* Wv  = (const float*)d_in[6];
    const float* bv  = (const float*)d_in[7];
    const float* We  = (const float*)d_in[8];
    const float* Wsk = (const float*)d_in[9];
    const float* bsk = (const float*)d_in[10];
    const float* Wg  = (const float*)d_in[11];
    const float* bg  = (const float*)d_in[12];
    const int*   ei  = (const int*)d_in[13];
    float* out = (float*)d_out;

    zero_kernel<<<(NN + 255) / 256, 256>>>();
    hist_kernel<<<(NE + 255) / 256, 256>>>(ei, ea);
    scan_kernel<<<1, 1024>>>();
    dis_kernel<<<(NN + 255) / 256, 256>>>();
    scatter_kernel<<<(NE + 255) / 256, 256>>>(ei, ea, We);
    qkv_kernel<<<400, 256>>>(x, Wq, bq, Wk, bk, Wv, bv, Wsk, bsk);
    attn_kernel<<<(NN * 32 + 255) / 256, 256>>>();
    hw_kernel<<<296, 256>>>(Wg);
    final_kernel<<<(NN * 32 + 255) / 256, 256>>>(bg, out);
}

// round 3
// speedup vs baseline: 2.0140x; 1.2621x over previous
#include <cuda_runtime.h>
#include <cuda_fp16.h>
#include <math.h>

#define NN 50000
#define NE 1600000

// ---------------- scratch (static device arrays) -----------------------------
__device__ __half d_Qh[NN * 256];       // [n][band(8)][hc(32)] q pre-scaled by 0.25*log2e
__device__ __half d_Kh[NN * 256];
__device__ __half d_Vh[NN * 256];
__device__ float  d_H[NN * 256];        // skip first, then h (post-ELU)
__device__ float  d_HW[NN * 32];
__device__ float4 d_csr[NE];            // {src(int bits), ax, ay, dis[src]*ay}
__device__ int    d_count[NN];
__device__ int    d_cursor[NN];
__device__ int    d_offsets[NN + 1];
__device__ float  d_degw[NN];
__device__ float  d_dis[NN];

__device__ __forceinline__ float ex2f(float x) {
    float y; asm("ex2.approx.f32 %0, %1;" : "=f"(y) : "f"(x)); return y;
}

// ---------------- CSR build --------------------------------------------------
__global__ void zero_kernel() {
    int i = blockIdx.x * blockDim.x + threadIdx.x;
    if (i < NN) { d_count[i] = 0; d_cursor[i] = 0; d_degw[i] = 0.f; }
}

__global__ void hist_kernel(const int* __restrict__ ei, const float* __restrict__ ea) {
    int e = blockIdx.x * blockDim.x + threadIdx.x;
    if (e < NE) {
        int dst = ei[NE + e];
        atomicAdd(&d_count[dst], 1);
        atomicAdd(&d_degw[dst], ea[2 * e + 1]);
    }
}

__global__ void scan_kernel() {
    __shared__ int wsum[32];
    __shared__ int carry;
    int tid = threadIdx.x, lane = tid & 31, wid = tid >> 5;
    if (tid == 0) carry = 0;
    __syncthreads();
    for (int base = 0; base < NN; base += 1024) {
        int i = base + tid;
        int v = (i < NN) ? d_count[i] : 0;
        int s = v;
        #pragma unroll
        for (int off = 1; off < 32; off <<= 1) {
            int t = __shfl_up_sync(0xffffffffu, s, off);
            if (lane >= off) s += t;
        }
        if (lane == 31) wsum[wid] = s;
        __syncthreads();
        if (wid == 0) {
            int ws = wsum[lane];
            #pragma unroll
            for (int off = 1; off < 32; off <<= 1) {
                int t = __shfl_up_sync(0xffffffffu, ws, off);
                if (lane >= off) ws += t;
            }
            wsum[lane] = ws;
        }
        __syncthreads();
        int wexcl = wid ? wsum[wid - 1] : 0;
        if (i < NN) d_offsets[i] = carry + wexcl + (s - v);
        int tot = wsum[31];
        __syncthreads();
        if (tid == 0) carry += tot;
        __syncthreads();
    }
    if (threadIdx.x == 0) d_offsets[NN] = carry;
}

__global__ void dis_kernel() {
    int i = blockIdx.x * blockDim.x + threadIdx.x;
    if (i < NN) d_dis[i] = rsqrtf(d_degw[i] + 2.0f);
}

__global__ void scatter_kernel(const int* __restrict__ ei, const float* __restrict__ ea) {
    int e = blockIdx.x * blockDim.x + threadIdx.x;
    if (e < NE) {
        int src = ei[e], dst = ei[NE + e];
        int pos = d_offsets[dst] + atomicAdd(&d_cursor[dst], 1);
        float ax = ea[2 * e], ay = ea[2 * e + 1];
        float4 pk;
        pk.x = __int_as_float(src);
        pk.y = ax;
        pk.z = ay;
        pk.w = d_dis[src] * ay;
        d_csr[pos] = pk;
    }
}

// ---------------- QKV + skip precompute, layout [n][band][hc] ----------------
__global__ void qkv_kernel(const float* __restrict__ x,
                           const float* __restrict__ Wq, const float* __restrict__ bq,
                           const float* __restrict__ Wk, const float* __restrict__ bk,
                           const float* __restrict__ Wv, const float* __restrict__ bv,
                           const float* __restrict__ Wsk, const float* __restrict__ bsk) {
    int lane = threadIdx.x & 31;
    int warp = (blockIdx.x * blockDim.x + threadIdx.x) >> 5;
    int nwarps = (gridDim.x * blockDim.x) >> 5;
    float wq[8], wk[8], wv[8], ws[8];
    #pragma unroll
    for (int i = 0; i < 8; i++) {
        wq[i] = Wq[i * 32 + lane];
        wk[i] = Wk[i * 32 + lane];
        wv[i] = Wv[i * 32 + lane];
        ws[i] = Wsk[i * 32 + lane];
    }
    float bqv = bq[lane], bkv = bk[lane], bvv = bv[lane], bsv = bsk[lane];
    const float QS = 0.25f * 1.4426950408889634f;  // 1/sqrt(16) * log2(e)

    for (int n = warp; n < NN; n += nwarps) {
        float x0 = x[n * 64 + lane];
        float x1 = x[n * 64 + 32 + lane];
        #pragma unroll
        for (int b = 0; b < 8; b++) {
            float aq = bqv, ak = bkv, av = bvv, asv = bsv;
            #pragma unroll
            for (int i = 0; i < 8; i++) {
                const int f = b * 8 + i;
                float xv = __shfl_sync(0xffffffffu, (f < 32) ? x0 : x1, f & 31);
                aq += xv * wq[i]; ak += xv * wk[i]; av += xv * wv[i]; asv += xv * ws[i];
            }
            int o = n * 256 + b * 32 + lane;
            d_Qh[o] = __float2half(aq * QS);
            d_Kh[o] = __float2half(ak);
            d_Vh[o] = __float2half(av);
            d_H[o]  = asv;
        }
    }
}

// ---------------- attention ---------------------------------------------------
// warp per dst; lane owns one (band,head) 16-ch slice; half-warps split edges;
// 2-edge unroll per half-warp -> 4 edges in flight per warp.
struct EdgeRes { float p; float ve[16]; };

__device__ __forceinline__ void edge_eval(
    int src, float ax, float ay, int pair,
    const __half2* q, const __half2* w0, const __half2* w1, EdgeRes& r)
{
    const uint4* kp = (const uint4*)&d_Kh[src * 256 + pair * 16];
    uint4 ku0 = kp[0], ku1 = kp[1];
    const uint4* vp = (const uint4*)&d_Vh[src * 256 + pair * 16];
    uint4 vu0 = vp[0], vu1 = vp[1];
    __half2 kh[8], vh[8];
    kh[0] = *(__half2*)&ku0.x; kh[1] = *(__half2*)&ku0.y; kh[2] = *(__half2*)&ku0.z; kh[3] = *(__half2*)&ku0.w;
    kh[4] = *(__half2*)&ku1.x; kh[5] = *(__half2*)&ku1.y; kh[6] = *(__half2*)&ku1.z; kh[7] = *(__half2*)&ku1.w;
    vh[0] = *(__half2*)&vu0.x; vh[1] = *(__half2*)&vu0.y; vh[2] = *(__half2*)&vu0.z; vh[3] = *(__half2*)&vu0.w;
    vh[4] = *(__half2*)&vu1.x; vh[5] = *(__half2*)&vu1.y; vh[6] = *(__half2*)&vu1.z; vh[7] = *(__half2*)&vu1.w;

    __half2 axh = __float2half2_rn(ax);
    __half2 ayh = __float2half2_rn(ay);
    __half2 d = __float2half2_rn(0.f);
    __half2 veh[8];
    #pragma unroll
    for (int i = 0; i < 8; i++) {
        __half2 eh = __hfma2(axh, w0[i], __hmul2(ayh, w1[i]));
        d = __hfma2(q[i], __hadd2(kh[i], eh), d);
        veh[i] = __hadd2(vh[i], eh);
    }
    float2 df = __half22float2(d);
    r.p = ex2f(df.x + df.y);
    #pragma unroll
    for (int i = 0; i < 8; i++) {
        float2 f = __half22float2(veh[i]);
        r.ve[2 * i]     = f.x;
        r.ve[2 * i + 1] = f.y;
    }
}

__global__ void __launch_bounds__(256, 2) attn_kernel(const float* __restrict__ We) {
    int tid = blockIdx.x * blockDim.x + threadIdx.x;
    int dst = tid >> 5;
    if (dst >= NN) return;
    int lane = threadIdx.x & 31;
    int pair = lane & 15;          // (band<<1)|head
    int hf   = lane >> 4;
    int hoff = (pair & 1) << 4;    // head*16 channel offset for We

    __half2 w0[8], w1[8], q[8];
    #pragma unroll
    for (int i = 0; i < 8; i++) {
        w0[i] = __floats2half2_rn(We[hoff + 2 * i],      We[hoff + 2 * i + 1]);
        w1[i] = __floats2half2_rn(We[32 + hoff + 2 * i], We[32 + hoff + 2 * i + 1]);
    }
    {
        const uint4* Qp = (const uint4*)&d_Qh[dst * 256 + pair * 16];
        uint4 qu0 = Qp[0], qu1 = Qp[1];
        q[0] = *(__half2*)&qu0.x; q[1] = *(__half2*)&qu0.y; q[2] = *(__half2*)&qu0.z; q[3] = *(__half2*)&qu0.w;
        q[4] = *(__half2*)&qu1.x; q[5] = *(__half2*)&qu1.y; q[6] = *(__half2*)&qu1.z; q[7] = *(__half2*)&qu1.w;
    }

    float acc[16];
    #pragma unroll
    for (int c = 0; c < 16; c++) acc[c] = 0.f;
    float z = 0.f;

    int start = d_offsets[dst], end = d_offsets[dst + 1];
    for (int e0 = start + hf; e0 < end; e0 += 4) {
        int e1 = e0 + 2;
        bool has1 = (e1 < end);
        int e1c = has1 ? e1 : e0;
        float4 pkA = d_csr[e0];
        float4 pkB = d_csr[e1c];
        int srcA = __float_as_int(pkA.x);
        int srcB = __float_as_int(pkB.x);
        EdgeRes A, B;
        edge_eval(srcA, pkA.y, pkA.z, pair, q, w0, w1, A);
        edge_eval(srcB, pkB.y, pkB.z, pair, q, w0, w1, B);
        if (!has1) B.p = 0.f;
        z += A.p + B.p;
        #pragma unroll
        for (int c = 0; c < 16; c++) {
            acc[c] = fmaf(A.p, A.ve[c], acc[c]);
            acc[c] = fmaf(B.p, B.ve[c], acc[c]);
        }
    }

    z += __shfl_xor_sync(0xffffffffu, z, 16);
    #pragma unroll
    for (int c = 0; c < 16; c++) acc[c] += __shfl_xor_sync(0xffffffffu, acc[c], 16);

    if (hf == 0) {
        float rz = (z > 0.f) ? 1.0f / z : 0.f;
        const float* Hp = &d_H[dst * 256 + pair * 16];
        float o[16];
        #pragma unroll
        for (int c = 0; c < 16; c++) {
            float t = fmaf(acc[c], rz, Hp[c]);
            o[c] = (t > 0.f) ? t : 0.1f * (__expf(t) - 1.0f);
        }
        float4* Op = (float4*)&d_H[dst * 256 + pair * 16];
        Op[0] = make_float4(o[0], o[1], o[2], o[3]);
        Op[1] = make_float4(o[4], o[5], o[6], o[7]);
        Op[2] = make_float4(o[8], o[9], o[10], o[11]);
        Op[3] = make_float4(o[12], o[13], o[14], o[15]);
    }
}

// ---------------- hw = h @ Wg -------------------------------------------------
__global__ void hw_kernel(const float* __restrict__ Wg) {
    __shared__ float wgs[256 * 32];
    for (int idx = threadIdx.x; idx < 8192; idx += blockDim.x)
        wgs[idx] = Wg[idx];
    __syncthreads();
    int lane = threadIdx.x & 31;
    int warp = (blockIdx.x * blockDim.x + threadIdx.x) >> 5;
    int nwarps = (gridDim.x * blockDim.x) >> 5;
    for (int n = warp; n < NN; n += nwarps) {
        const float4* Hp = (const float4*)&d_H[n * 256];
        float a = 0.f;
        #pragma unroll
        for (int c = 0; c < 64; c++) {
            float4 hv = Hp[c];  // uniform per warp -> broadcast
            a += hv.x * wgs[(4 * c + 0) * 32 + lane];
            a += hv.y * wgs[(4 * c + 1) * 32 + lane];
            a += hv.z * wgs[(4 * c + 2) * 32 + lane];
            a += hv.w * wgs[(4 * c + 3) * 32 + lane];
        }
        d_HW[n * 32 + lane] = a;
    }
}

// ---------------- final normalized propagation -------------------------------
__global__ void final_kernel(const float* __restrict__ bg, float* __restrict__ out) {
    int lane = threadIdx.x & 31;
    int dst = (blockIdx.x * blockDim.x + threadIdx.x) >> 5;
    if (dst >= NN) return;
    float dd = d_dis[dst];
    float acc = 2.0f * dd * d_HW[dst * 32 + lane];  // self loop
    int start = d_offsets[dst], end = d_offsets[dst + 1];
    for (int t = start; t < end; t++) {
        float4 pk = d_csr[t];              // uniform across warp -> broadcast
        int src = __float_as_int(pk.x);
        acc = fmaf(pk.w, d_HW[src * 32 + lane], acc);
    }
    out[dst * 32 + lane] = bg[lane] + dd * acc;
}

// ---------------- launch -----------------------------------------------------
extern "C" void kernel_launch(void* const* d_in, const int* in_sizes, int n_in,
                              void* d_out, int out_size) {
    const float* x   = (const float*)d_in[0];
    const float* ea  = (const float*)d_in[1];
    const float* Wq  = (const float*)d_in[2];
    const float* bq  = (const float*)d_in[3];
    const float* Wk  = (const float*)d_in[4];
    const float* bk  = (const float*)d_in[5];
    const float* Wv  = (const float*)d_in[6];
    const float* bv  = (const float*)d_in[7];
    const float* We  = (const float*)d_in[8];
    const float* Wsk = (const float*)d_in[9];
    const float* bsk = (const float*)d_in[10];
    const float* Wg  = (const float*)d_in[11];
    const float* bg  = (const float*)d_in[12];
    const int*   ei  = (const int*)d_in[13];
    float* out = (float*)d_out;

    zero_kernel<<<(NN + 255) / 256, 256>>>();
    hist_kernel<<<(NE + 255) / 256, 256>>>(ei, ea);
    scan_kernel<<<1, 1024>>>();
    dis_kernel<<<(NN + 255) / 256, 256>>>();
    scatter_kernel<<<(NE + 255) / 256, 256>>>(ei, ea);
    qkv_kernel<<<400, 256>>>(x, Wq, bq, Wk, bk, Wv, bv, Wsk, bsk);
    attn_kernel<<<(NN * 32 + 255) / 256, 256>>>(We);
    hw_kernel<<<296, 256>>>(Wg);
    final_kernel<<<(NN * 32 + 255) / 256, 256>>>(bg, out);
}